// round 5
// baseline (speedup 1.0000x reference)
#include <cuda_runtime.h>
#include <cuda_bf16.h>
#include <cstdint>

// Problem constants (fixed by the reference setup)
#define NN 100000
#define EE 3200000
#define GB 1563            // 64-row tiles: ceil(NN/64)

// ---------------- device scratch (no allocations allowed) ----------------
__device__ int   g_deg[NN];
__device__ int   g_off[NN];
__device__ int   g_cursor[NN];
__device__ int   g_bsum[1024];
__device__ uint2 g_epack[EE];               // (col, bits(w)) packed 8B
__device__ float g_y1[(size_t)NN * 128];    // feat @ W1

// ---------------- CSR build helpers ----------------
__global__ void k_zero_deg() {
    int i = blockIdx.x * blockDim.x + threadIdx.x;
    if (i < NN) g_deg[i] = 0;
}

__global__ void k_hist(const int* __restrict__ rows) {
    int e = blockIdx.x * blockDim.x + threadIdx.x;
    if (e < EE) atomicAdd(&g_deg[rows[e]], 1);
}

// block-level exclusive scan (1024 threads = 32 warps)
__global__ void k_scan_block(const int* __restrict__ in, int* __restrict__ out,
                             int* __restrict__ bsum, int n) {
    __shared__ int warpSums[32];
    int i = blockIdx.x * 1024 + threadIdx.x;
    int lane = threadIdx.x & 31, wid = threadIdx.x >> 5;
    int v = (i < n) ? in[i] : 0;
    int s = v;
    #pragma unroll
    for (int o = 1; o < 32; o <<= 1) {
        int t = __shfl_up_sync(0xffffffffu, s, o);
        if (lane >= o) s += t;
    }
    if (lane == 31) warpSums[wid] = s;
    __syncthreads();
    if (wid == 0) {
        int ws = warpSums[lane];
        #pragma unroll
        for (int o = 1; o < 32; o <<= 1) {
            int t = __shfl_up_sync(0xffffffffu, ws, o);
            if (lane >= o) ws += t;
        }
        warpSums[lane] = ws;
    }
    __syncthreads();
    int excl = s - v + ((wid > 0) ? warpSums[wid - 1] : 0);
    if (i < n) out[i] = excl;
    if (threadIdx.x == 1023 && bsum) bsum[blockIdx.x] = excl + v;
}

__global__ void k_finalize_off() {
    int i = blockIdx.x * blockDim.x + threadIdx.x;
    if (i < NN) {
        int o = g_off[i] + g_bsum[i >> 10];
        g_off[i] = o;
        g_cursor[i] = o;
    }
}

// ---------------- shared GEMM macro-body: acc[8][4] = Xtile @ W ----------------
// block = 256 threads = 8 warps; tile = 64 rows; warp = 8 rows x 128 cols;
// lane owns cols [4*lane, 4*lane+4). Round-1-proven fp32 FFMA body.
__device__ __forceinline__ void gemm_tile(
    int rowBase, const float* __restrict__ X, const float* __restrict__ W,
    float* sW, float* sX, float acc[8][4])
{
    for (int i = threadIdx.x; i < 128 * 32; i += 256)
        ((float4*)sW)[i] = ((const float4*)W)[i];
    for (int i = threadIdx.x; i < 64 * 32; i += 256) {
        int r = i >> 5, kk = i & 31;
        float4 v = make_float4(0.f, 0.f, 0.f, 0.f);
        int gr = rowBase + r;
        if (gr < NN) v = ((const float4*)(X + (size_t)gr * 128))[kk];
        ((float4*)sX)[i] = v;
    }
    __syncthreads();

    const int warp = threadIdx.x >> 5, lane = threadIdx.x & 31;
    #pragma unroll
    for (int r = 0; r < 8; r++)
        #pragma unroll
        for (int c = 0; c < 4; c++) acc[r][c] = 0.f;

    const float* xbase = sX + (warp * 8) * 128;

    #pragma unroll 1
    for (int k = 0; k < 128; k += 4) {
        float4 wv0 = *(const float4*)(sW + (k + 0) * 128 + 4 * lane);
        float4 wv1 = *(const float4*)(sW + (k + 1) * 128 + 4 * lane);
        float4 wv2 = *(const float4*)(sW + (k + 2) * 128 + 4 * lane);
        float4 wv3 = *(const float4*)(sW + (k + 3) * 128 + 4 * lane);
        #pragma unroll
        for (int r = 0; r < 8; r++) {
            float4 xv = *(const float4*)(xbase + r * 128 + k);
            acc[r][0] = fmaf(xv.x, wv0.x, acc[r][0]);
            acc[r][1] = fmaf(xv.x, wv0.y, acc[r][1]);
            acc[r][2] = fmaf(xv.x, wv0.z, acc[r][2]);
            acc[r][3] = fmaf(xv.x, wv0.w, acc[r][3]);
            acc[r][0] = fmaf(xv.y, wv1.x, acc[r][0]);
            acc[r][1] = fmaf(xv.y, wv1.y, acc[r][1]);
            acc[r][2] = fmaf(xv.y, wv1.z, acc[r][2]);
            acc[r][3] = fmaf(xv.y, wv1.w, acc[r][3]);
            acc[r][0] = fmaf(xv.z, wv2.x, acc[r][0]);
            acc[r][1] = fmaf(xv.z, wv2.y, acc[r][1]);
            acc[r][2] = fmaf(xv.z, wv2.z, acc[r][2]);
            acc[r][3] = fmaf(xv.z, wv2.w, acc[r][3]);
            acc[r][0] = fmaf(xv.w, wv3.x, acc[r][0]);
            acc[r][1] = fmaf(xv.w, wv3.y, acc[r][1]);
            acc[r][2] = fmaf(xv.w, wv3.z, acc[r][2]);
            acc[r][3] = fmaf(xv.w, wv3.w, acc[r][3]);
        }
    }
}

// relu + rownorm epilogue on a 4-lane slice; returns normalized float4
__device__ __forceinline__ float4 norm_epi(
    float a0, float a1, float a2, float a3,
    const float4& bv, const float4& scv, const float4& ofv)
{
    float h0 = fmaxf(a0 + bv.x, 0.f);
    float h1 = fmaxf(a1 + bv.y, 0.f);
    float h2 = fmaxf(a2 + bv.z, 0.f);
    float h3 = fmaxf(a3 + bv.w, 0.f);
    float s = h0 + h1 + h2 + h3;
    #pragma unroll
    for (int o = 16; o; o >>= 1) s += __shfl_xor_sync(0xffffffffu, s, o);
    float mean = s * (1.f / 128.f);
    float d0 = h0 - mean, d1 = h1 - mean, d2 = h2 - mean, d3 = h3 - mean;
    float q = d0 * d0 + d1 * d1 + d2 * d2 + d3 * d3;
    #pragma unroll
    for (int o = 16; o; o >>= 1) q += __shfl_xor_sync(0xffffffffu, q, o);
    float inv = rsqrtf(q * (1.f / 128.f) + 1e-9f);
    float4 r;
    r.x = d0 * scv.x * inv + ofv.x;
    r.y = d1 * scv.y * inv + ofv.y;
    r.z = d2 * scv.z * inv + ofv.z;
    r.w = d3 * scv.w * inv + ofv.w;
    return r;
}

// ---------------- fused middle kernel: {gemm_y1, scatter} concurrently ----------------
// 1:1 interleave: even blocks do one 64-row y1 tile, odd blocks scatter 2048 edges.
// grid = 2*GB = 3126. GB*2048 = 3,201,024 >= EE.
__global__ __launch_bounds__(256) void fused_mid(
    const float* __restrict__ feat, const float* __restrict__ W1,
    const int* __restrict__ rows, const int* __restrict__ cols,
    const float* __restrict__ vals, float* __restrict__ y1)
{
    extern __shared__ float smem[];
    int bid = blockIdx.x;
    int g = bid >> 1;
    if ((bid & 1) == 0) {
        float acc[8][4];
        gemm_tile(g * 64, feat, W1, smem, smem + 128 * 128, acc);
        const int warp = threadIdx.x >> 5, lane = threadIdx.x & 31;
        const int warpRow = g * 64 + warp * 8;
        #pragma unroll
        for (int r = 0; r < 8; r++) {
            int row = warpRow + r;
            if (row >= NN) break;
            float4 o4 = make_float4(acc[r][0], acc[r][1], acc[r][2], acc[r][3]);
            *(float4*)(y1 + (size_t)row * 128 + 4 * lane) = o4;
        }
    } else {
        int base = g * 2048 + (int)threadIdx.x;
        #pragma unroll
        for (int j = 0; j < 8; j++) {
            int e = base + j * 256;
            if (e < EE) {
                int rr = rows[e];
                int p = atomicAdd(&g_cursor[rr], 1);
                g_epack[p] = make_uint2((unsigned)cols[e], __float_as_uint(vals[e]));
            }
        }
    }
}

// ---------------- fused tail: p0 GEMM (fma) + p1 gather (mem) + single write ----
// Same 64-row tiling as gemm_tile; after the FFMA phase each warp gathers its
// 8 rows. The p0 FMA work hides under the gather's memory stalls of other warps.
__global__ __launch_bounds__(256) void spmm_fused(
    const float* __restrict__ feat, const float* __restrict__ W0,
    const float* __restrict__ b0, const float* __restrict__ off0,
    const float* __restrict__ sc0,
    const float* __restrict__ b1, const float* __restrict__ off1,
    const float* __restrict__ sc1, float* __restrict__ out)
{
    extern __shared__ float smem[];
    const int warp = threadIdx.x >> 5, lane = threadIdx.x & 31;
    const int rowBase = blockIdx.x * 64;

    // ---- phase 1: p0 = norm(relu(feat@W0 + b0)) for this tile, stashed in regs
    float acc[8][4];
    gemm_tile(rowBase, feat, W0, smem, smem + 128 * 128, acc);

    float4 bv0  = *(const float4*)(b0  + 4 * lane);
    float4 scv0 = *(const float4*)(sc0 + 4 * lane);
    float4 ofv0 = *(const float4*)(off0 + 4 * lane);
    float4 p0s[8];
    #pragma unroll
    for (int r = 0; r < 8; r++)
        p0s[r] = norm_epi(acc[r][0], acc[r][1], acc[r][2], acc[r][3], bv0, scv0, ofv0);

    // ---- phase 2: per-warp gather of p1 rows, combine, single store
    float4 bv1  = *(const float4*)(b1  + 4 * lane);
    float4 scv1 = *(const float4*)(sc1 + 4 * lane);
    float4 ofv1 = *(const float4*)(off1 + 4 * lane);

    const int warpRow = rowBase + warp * 8;
    #pragma unroll 1
    for (int r = 0; r < 8; r++) {
        int row = warpRow + r;
        if (row >= NN) break;
        int start = g_off[row];
        int deg   = g_deg[row];

        float4 a = make_float4(0.f, 0.f, 0.f, 0.f);
        for (int base = 0; base < deg; base += 32) {
            int idx = base + lane;
            uint2 ew = make_uint2(0u, 0u);
            if (idx < deg) ew = g_epack[start + idx];
            int m = min(32, deg - base);
            #pragma unroll 8
            for (int j = 0; j < m; j++) {
                int   cj = (int)__shfl_sync(0xffffffffu, ew.x, j);
                float wj = __int_as_float(__shfl_sync(0xffffffffu, ew.y, j));
                float4 y = *(const float4*)(g_y1 + (size_t)cj * 128 + 4 * lane);
                a.x = fmaf(wj, y.x, a.x);
                a.y = fmaf(wj, y.y, a.y);
                a.z = fmaf(wj, y.z, a.z);
                a.w = fmaf(wj, y.w, a.w);
            }
        }
        float4 p1 = norm_epi(a.x, a.y, a.z, a.w, bv1, scv1, ofv1);
        float4 o4;
        o4.x = p0s[r].x + p1.x;
        o4.y = p0s[r].y + p1.y;
        o4.z = p0s[r].z + p1.z;
        o4.w = p0s[r].w + p1.w;
        *(float4*)(out + (size_t)row * 128 + 4 * lane) = o4;
    }
}

// ---------------- launcher ----------------
extern "C" void kernel_launch(void* const* d_in, const int* in_sizes, int n_in,
                              void* d_out, int out_size)
{
    const float* feat = (const float*)d_in[0];
    const float* vals = (const float*)d_in[1];
    const float* W0   = (const float*)d_in[2];
    const float* b0   = (const float*)d_in[3];
    const float* off0 = (const float*)d_in[4];
    const float* sc0  = (const float*)d_in[5];
    const float* W1   = (const float*)d_in[6];
    const float* b1   = (const float*)d_in[7];
    const float* off1 = (const float*)d_in[8];
    const float* sc1  = (const float*)d_in[9];
    const int*   rows = (const int*)d_in[10];
    const int*   cols = (const int*)d_in[11];
    float* out = (float*)d_out;

    const int smem = (128 * 128 + 64 * 128) * (int)sizeof(float); // 96 KB
    cudaFuncSetAttribute(fused_mid,  cudaFuncAttributeMaxDynamicSharedMemorySize, smem);
    cudaFuncSetAttribute(spmm_fused, cudaFuncAttributeMaxDynamicSharedMemorySize, smem);

    // ---- CSR front chain (serial, small) ----
    k_zero_deg<<<(NN + 255) / 256, 256>>>();
    k_hist<<<(EE + 255) / 256, 256>>>(rows);
    int nblk = (NN + 1023) / 1024;           // 98
    {
        int* offp;  cudaGetSymbolAddress((void**)&offp,  g_off);
        int* degp;  cudaGetSymbolAddress((void**)&degp,  g_deg);
        int* bsump; cudaGetSymbolAddress((void**)&bsump, g_bsum);
        k_scan_block<<<nblk, 1024>>>(degp, offp, bsump, NN);
        k_scan_block<<<1, 1024>>>(bsump, bsump, nullptr, nblk);
    }
    k_finalize_off<<<(NN + 255) / 256, 256>>>();

    // ---- middle: y1 GEMM + edge scatter concurrently ----
    float* y1p; cudaGetSymbolAddress((void**)&y1p, g_y1);
    fused_mid<<<2 * GB, 256, smem>>>(feat, W1, rows, cols, vals, y1p);

    // ---- tail: p0 GEMM under p1 gather, single write of out ----
    spmm_fused<<<GB, 256, smem>>>(feat, W0, b0, off0, sc0, b1, off1, sc1, out);
}

// round 6
// speedup vs baseline: 1.5332x; 1.5332x over previous
#include <cuda_runtime.h>
#include <cuda_fp16.h>
#include <cstdint>

// Problem constants (fixed by the reference setup)
#define NN 100000
#define EE 3200000
#define GB 1563            // GEMM blocks per matrix: ceil(NN/64)

// ---------------- device scratch (no allocations allowed) ----------------
__device__ int    g_deg[NN];
__device__ int    g_off[NN];
__device__ int    g_cursor[NN];
__device__ int    g_bsum[1024];
__device__ uint2  g_epack[EE];                 // (col, bits(w)) packed 8B
__device__ __half g_y1h[(size_t)NN * 128];     // feat @ W1, fp16 (halved gather bytes)

// ---------------- CSR build helpers ----------------
__global__ void k_zero_deg() {
    int i = blockIdx.x * blockDim.x + threadIdx.x;
    if (i < NN) g_deg[i] = 0;
}

__global__ void k_hist(const int* __restrict__ rows) {
    int e = blockIdx.x * blockDim.x + threadIdx.x;
    if (e < EE) atomicAdd(&g_deg[rows[e]], 1);
}

// block-level exclusive scan (1024 threads = 32 warps)
__global__ void k_scan_block(const int* __restrict__ in, int* __restrict__ out,
                             int* __restrict__ bsum, int n) {
    __shared__ int warpSums[32];
    int i = blockIdx.x * 1024 + threadIdx.x;
    int lane = threadIdx.x & 31, wid = threadIdx.x >> 5;
    int v = (i < n) ? in[i] : 0;
    int s = v;
    #pragma unroll
    for (int o = 1; o < 32; o <<= 1) {
        int t = __shfl_up_sync(0xffffffffu, s, o);
        if (lane >= o) s += t;
    }
    if (lane == 31) warpSums[wid] = s;
    __syncthreads();
    if (wid == 0) {
        int ws = warpSums[lane];
        #pragma unroll
        for (int o = 1; o < 32; o <<= 1) {
            int t = __shfl_up_sync(0xffffffffu, ws, o);
            if (lane >= o) ws += t;
        }
        warpSums[lane] = ws;
    }
    __syncthreads();
    int excl = s - v + ((wid > 0) ? warpSums[wid - 1] : 0);
    if (i < n) out[i] = excl;
    if (threadIdx.x == 1023 && bsum) bsum[blockIdx.x] = excl + v;
}

__global__ void k_finalize_off() {
    int i = blockIdx.x * blockDim.x + threadIdx.x;
    if (i < NN) {
        int o = g_off[i] + g_bsum[i >> 10];
        g_off[i] = o;
        g_cursor[i] = o;
    }
}

// ---------------- dense GEMM body: acc = X[64,128] @ W[128,128] (+ fused epi) ----
// block = 256 threads = 8 warps; block tile = 64 rows; warp tile = 8 rows x 128 cols;
// lane owns cols [4*lane, 4*lane+4). (Round-1/4-proven fp32 FFMA body.)
// EPI=true : relu+rownorm epilogue, fp32 store to out.
// EPI=false: raw accumulators converted to fp16, 8B store to y1h.
template <bool EPI>
__device__ __forceinline__ void gemm_body(
    int blk, const float* __restrict__ X, const float* __restrict__ W,
    const float* __restrict__ b, const float* __restrict__ off,
    const float* __restrict__ sc, float* __restrict__ out,
    __half* __restrict__ outh, float* smem)
{
    float* sW = smem;               // 128*128
    float* sX = smem + 128 * 128;   // 64*128

    const int warp = threadIdx.x >> 5, lane = threadIdx.x & 31;
    const int rowBase = blk * 64;

    // load W (16384 floats = 4096 float4, 16 per thread)
    for (int i = threadIdx.x; i < 128 * 32; i += 256)
        ((float4*)sW)[i] = ((const float4*)W)[i];
    // load X tile (64 rows, zero-pad tail)
    for (int i = threadIdx.x; i < 64 * 32; i += 256) {
        int r = i >> 5, kk = i & 31;
        float4 v = make_float4(0.f, 0.f, 0.f, 0.f);
        int gr = rowBase + r;
        if (gr < NN) v = ((const float4*)(X + (size_t)gr * 128))[kk];
        ((float4*)sX)[i] = v;
    }
    __syncthreads();

    float acc[8][4];
    #pragma unroll
    for (int r = 0; r < 8; r++)
        #pragma unroll
        for (int c = 0; c < 4; c++) acc[r][c] = 0.f;

    const float* xbase = sX + (warp * 8) * 128;

    #pragma unroll 1
    for (int k = 0; k < 128; k += 4) {
        float4 wv0 = *(const float4*)(sW + (k + 0) * 128 + 4 * lane);
        float4 wv1 = *(const float4*)(sW + (k + 1) * 128 + 4 * lane);
        float4 wv2 = *(const float4*)(sW + (k + 2) * 128 + 4 * lane);
        float4 wv3 = *(const float4*)(sW + (k + 3) * 128 + 4 * lane);
        #pragma unroll
        for (int r = 0; r < 8; r++) {
            float4 xv = *(const float4*)(xbase + r * 128 + k);
            acc[r][0] = fmaf(xv.x, wv0.x, acc[r][0]);
            acc[r][1] = fmaf(xv.x, wv0.y, acc[r][1]);
            acc[r][2] = fmaf(xv.x, wv0.z, acc[r][2]);
            acc[r][3] = fmaf(xv.x, wv0.w, acc[r][3]);
            acc[r][0] = fmaf(xv.y, wv1.x, acc[r][0]);
            acc[r][1] = fmaf(xv.y, wv1.y, acc[r][1]);
            acc[r][2] = fmaf(xv.y, wv1.z, acc[r][2]);
            acc[r][3] = fmaf(xv.y, wv1.w, acc[r][3]);
            acc[r][0] = fmaf(xv.z, wv2.x, acc[r][0]);
            acc[r][1] = fmaf(xv.z, wv2.y, acc[r][1]);
            acc[r][2] = fmaf(xv.z, wv2.z, acc[r][2]);
            acc[r][3] = fmaf(xv.z, wv2.w, acc[r][3]);
            acc[r][0] = fmaf(xv.w, wv3.x, acc[r][0]);
            acc[r][1] = fmaf(xv.w, wv3.y, acc[r][1]);
            acc[r][2] = fmaf(xv.w, wv3.z, acc[r][2]);
            acc[r][3] = fmaf(xv.w, wv3.w, acc[r][3]);
        }
    }

    const int warpRow = rowBase + warp * 8;
    if (EPI) {
        float4 bv  = *(const float4*)(b  + 4 * lane);
        float4 scv = *(const float4*)(sc + 4 * lane);
        float4 ofv = *(const float4*)(off + 4 * lane);
        #pragma unroll
        for (int r = 0; r < 8; r++) {
            int row = warpRow + r;
            if (row >= NN) break;
            float h0 = fmaxf(acc[r][0] + bv.x, 0.f);
            float h1 = fmaxf(acc[r][1] + bv.y, 0.f);
            float h2 = fmaxf(acc[r][2] + bv.z, 0.f);
            float h3 = fmaxf(acc[r][3] + bv.w, 0.f);
            float s = h0 + h1 + h2 + h3;
            #pragma unroll
            for (int o = 16; o; o >>= 1) s += __shfl_xor_sync(0xffffffffu, s, o);
            float mean = s * (1.f / 128.f);
            float d0 = h0 - mean, d1 = h1 - mean, d2 = h2 - mean, d3 = h3 - mean;
            float q = d0 * d0 + d1 * d1 + d2 * d2 + d3 * d3;
            #pragma unroll
            for (int o = 16; o; o >>= 1) q += __shfl_xor_sync(0xffffffffu, q, o);
            float inv = rsqrtf(q * (1.f / 128.f) + 1e-9f);
            float4 o4;
            o4.x = d0 * scv.x * inv + ofv.x;
            o4.y = d1 * scv.y * inv + ofv.y;
            o4.z = d2 * scv.z * inv + ofv.z;
            o4.w = d3 * scv.w * inv + ofv.w;
            *(float4*)(out + (size_t)row * 128 + 4 * lane) = o4;
        }
    } else {
        #pragma unroll
        for (int r = 0; r < 8; r++) {
            int row = warpRow + r;
            if (row >= NN) break;
            __half2 h01 = __floats2half2_rn(acc[r][0], acc[r][1]);
            __half2 h23 = __floats2half2_rn(acc[r][2], acc[r][3]);
            uint2 pk;
            pk.x = *(unsigned*)&h01;
            pk.y = *(unsigned*)&h23;
            ((uint2*)(outh + (size_t)row * 128))[lane] = pk;
        }
    }
}

// ---------------- fused middle kernel: {gemm_p0, gemm_y1, scatter} concurrently ----
// 1:1 interleave: even blocks do one 64-row GEMM tile, odd blocks scatter 1024 edges.
// grid = 2 * 2 * GB = 6252 blocks. 2*GB*1024 = 3,201,024 >= EE.
__global__ __launch_bounds__(256) void fused_mid(
    const float* __restrict__ feat,
    const float* __restrict__ W0, const float* __restrict__ b0,
    const float* __restrict__ off0, const float* __restrict__ sc0,
    const float* __restrict__ W1,
    const int* __restrict__ rows, const int* __restrict__ cols,
    const float* __restrict__ vals,
    float* __restrict__ out, __half* __restrict__ y1h)
{
    extern __shared__ float smem[];
    int bid = blockIdx.x;
    int g = bid >> 1;
    if ((bid & 1) == 0) {
        if (g < GB) gemm_body<true >(g,      feat, W0, b0, off0, sc0, out, nullptr, smem);
        else        gemm_body<false>(g - GB, feat, W1, nullptr, nullptr, nullptr, nullptr, y1h, smem);
    } else {
        int base = g * 1024 + (int)threadIdx.x;
        #pragma unroll
        for (int j = 0; j < 4; j++) {
            int e = base + j * 256;
            if (e < EE) {
                int rr = rows[e];
                int p = atomicAdd(&g_cursor[rr], 1);
                g_epack[p] = make_uint2((unsigned)cols[e], __float_as_uint(vals[e]));
            }
        }
    }
}

// ---------------- SpMM gather + fused epilogue: out[r] += norm(relu(A@y1 + b1)) ----
// One warp per row; gathered y1 rows are fp16 (256B/row -> 8 sectors).
__global__ __launch_bounds__(256) void spmm_kernel(
    const float* __restrict__ b, const float* __restrict__ off,
    const float* __restrict__ sc, float* __restrict__ out)
{
    int gw = (blockIdx.x * blockDim.x + threadIdx.x) >> 5;
    if (gw >= NN) return;
    int lane = threadIdx.x & 31;
    int start = g_off[gw];
    int deg   = g_deg[gw];

    float4 acc = make_float4(0.f, 0.f, 0.f, 0.f);
    for (int base = 0; base < deg; base += 32) {
        int idx = base + lane;
        uint2 ew = make_uint2(0u, 0u);
        if (idx < deg) ew = g_epack[start + idx];
        int m = min(32, deg - base);
        #pragma unroll 4
        for (int j = 0; j < m; j++) {
            int   cj = (int)__shfl_sync(0xffffffffu, ew.x, j);
            float wj = __int_as_float(__shfl_sync(0xffffffffu, ew.y, j));
            uint2 yv = ((const uint2*)(g_y1h + (size_t)cj * 128))[lane];
            __half2 h01 = *(__half2*)&yv.x;
            __half2 h23 = *(__half2*)&yv.y;
            float2 f01 = __half22float2(h01);
            float2 f23 = __half22float2(h23);
            acc.x = fmaf(wj, f01.x, acc.x);
            acc.y = fmaf(wj, f01.y, acc.y);
            acc.z = fmaf(wj, f23.x, acc.z);
            acc.w = fmaf(wj, f23.y, acc.w);
        }
    }

    float4 bv  = *(const float4*)(b  + 4 * lane);
    float4 scv = *(const float4*)(sc + 4 * lane);
    float4 ofv = *(const float4*)(off + 4 * lane);
    float h0 = fmaxf(acc.x + bv.x, 0.f);
    float h1 = fmaxf(acc.y + bv.y, 0.f);
    float h2 = fmaxf(acc.z + bv.z, 0.f);
    float h3 = fmaxf(acc.w + bv.w, 0.f);
    float s = h0 + h1 + h2 + h3;
    #pragma unroll
    for (int o = 16; o; o >>= 1) s += __shfl_xor_sync(0xffffffffu, s, o);
    float mean = s * (1.f / 128.f);
    float d0 = h0 - mean, d1 = h1 - mean, d2 = h2 - mean, d3 = h3 - mean;
    float q = d0 * d0 + d1 * d1 + d2 * d2 + d3 * d3;
    #pragma unroll
    for (int o = 16; o; o >>= 1) q += __shfl_xor_sync(0xffffffffu, q, o);
    float inv = rsqrtf(q * (1.f / 128.f) + 1e-9f);

    float* orow = out + (size_t)gw * 128 + 4 * lane;
    float4 prev = *(float4*)orow;
    float4 o4;
    o4.x = prev.x + d0 * scv.x * inv + ofv.x;
    o4.y = prev.y + d1 * scv.y * inv + ofv.y;
    o4.z = prev.z + d2 * scv.z * inv + ofv.z;
    o4.w = prev.w + d3 * scv.w * inv + ofv.w;
    *(float4*)orow = o4;
}

// ---------------- launcher ----------------
extern "C" void kernel_launch(void* const* d_in, const int* in_sizes, int n_in,
                              void* d_out, int out_size)
{
    const float* feat = (const float*)d_in[0];
    const float* vals = (const float*)d_in[1];
    const float* W0   = (const float*)d_in[2];
    const float* b0   = (const float*)d_in[3];
    const float* off0 = (const float*)d_in[4];
    const float* sc0  = (const float*)d_in[5];
    const float* W1   = (const float*)d_in[6];
    const float* b1   = (const float*)d_in[7];
    const float* off1 = (const float*)d_in[8];
    const float* sc1  = (const float*)d_in[9];
    const int*   rows = (const int*)d_in[10];
    const int*   cols = (const int*)d_in[11];
    float* out = (float*)d_out;

    const int smem = (128 * 128 + 64 * 128) * (int)sizeof(float); // 96 KB
    cudaFuncSetAttribute(fused_mid, cudaFuncAttributeMaxDynamicSharedMemorySize, smem);

    // ---- CSR front chain (serial, small) ----
    k_zero_deg<<<(NN + 255) / 256, 256>>>();
    k_hist<<<(EE + 255) / 256, 256>>>(rows);
    int nblk = (NN + 1023) / 1024;           // 98
    {
        int* offp;  cudaGetSymbolAddress((void**)&offp,  g_off);
        int* degp;  cudaGetSymbolAddress((void**)&degp,  g_deg);
        int* bsump; cudaGetSymbolAddress((void**)&bsump, g_bsum);
        k_scan_block<<<nblk, 1024>>>(degp, offp, bsump, NN);
        k_scan_block<<<1, 1024>>>(bsump, bsump, nullptr, nblk);
    }
    k_finalize_off<<<(NN + 255) / 256, 256>>>();

    // ---- fused middle: both GEMMs + edge scatter concurrently ----
    __half* y1p; cudaGetSymbolAddress((void**)&y1p, g_y1h);
    fused_mid<<<2 * 2 * GB, 256, smem>>>(feat, W0, b0, off0, sc0, W1,
                                         rows, cols, vals, out, y1p);

    // ---- sparse aggregate + fused p1 epilogue, out += p1 ----
    int sblocks = ((NN * 32) + 255) / 256;   // one warp per row
    spmm_kernel<<<sblocks, 256>>>(b1, off1, sc1, out);
}

// round 7
// speedup vs baseline: 1.6708x; 1.0897x over previous
#include <cuda_runtime.h>
#include <cuda_fp16.h>
#include <cstdint>

// Problem constants (fixed by the reference setup)
#define NN 100000
#define EE 3200000
#define TB 1563            // 64-row GEMM tiles per matrix: ceil(NN/64)
#define PW 132             // padded smem row (words) -> conflict-free fragment LDS

// ---------------- device scratch (no allocations allowed) ----------------
__device__ int    g_deg[NN];
__device__ int    g_off[NN];
__device__ int    g_cursor[NN];
__device__ int    g_bsum[1024];
__device__ uint2  g_epack[EE];                 // (col, bits(w)) packed 8B
__device__ __half g_y1h[(size_t)NN * 128];     // feat @ W1, fp16

// ---------------- tf32 helpers ----------------
__device__ __forceinline__ unsigned f2tf32(float f) {
    unsigned r;
    asm("cvt.rna.tf32.f32 %0, %1;" : "=r"(r) : "f"(f));
    return r;
}
__device__ __forceinline__ void mma_tf32(float4& d,
    unsigned a0, unsigned a1, unsigned a2, unsigned a3,
    unsigned b0, unsigned b1)
{
    asm volatile(
        "mma.sync.aligned.m16n8k8.row.col.f32.tf32.tf32.f32 "
        "{%0,%1,%2,%3}, {%4,%5,%6,%7}, {%8,%9}, {%0,%1,%2,%3};"
        : "+f"(d.x), "+f"(d.y), "+f"(d.z), "+f"(d.w)
        : "r"(a0), "r"(a1), "r"(a2), "r"(a3), "r"(b0), "r"(b1));
}

// ---------------- CSR build helpers ----------------
__global__ void k_zero_deg() {
    int i = blockIdx.x * blockDim.x + threadIdx.x;
    if (i < NN) g_deg[i] = 0;
}

__global__ void k_hist(const int* __restrict__ rows) {
    int e = blockIdx.x * blockDim.x + threadIdx.x;
    if (e < EE) atomicAdd(&g_deg[rows[e]], 1);
}

// block-level exclusive scan (1024 threads = 32 warps)
__global__ void k_scan_block(const int* __restrict__ in, int* __restrict__ out,
                             int* __restrict__ bsum, int n) {
    __shared__ int warpSums[32];
    int i = blockIdx.x * 1024 + threadIdx.x;
    int lane = threadIdx.x & 31, wid = threadIdx.x >> 5;
    int v = (i < n) ? in[i] : 0;
    int s = v;
    #pragma unroll
    for (int o = 1; o < 32; o <<= 1) {
        int t = __shfl_up_sync(0xffffffffu, s, o);
        if (lane >= o) s += t;
    }
    if (lane == 31) warpSums[wid] = s;
    __syncthreads();
    if (wid == 0) {
        int ws = warpSums[lane];
        #pragma unroll
        for (int o = 1; o < 32; o <<= 1) {
            int t = __shfl_up_sync(0xffffffffu, ws, o);
            if (lane >= o) ws += t;
        }
        warpSums[lane] = ws;
    }
    __syncthreads();
    int excl = s - v + ((wid > 0) ? warpSums[wid - 1] : 0);
    if (i < n) out[i] = excl;
    if (threadIdx.x == 1023 && bsum) bsum[blockIdx.x] = excl + v;
}

__global__ void k_finalize_off() {
    int i = blockIdx.x * blockDim.x + threadIdx.x;
    if (i < NN) {
        int o = g_off[i] + g_bsum[i >> 10];
        g_off[i] = o;
        g_cursor[i] = o;
    }
}

// ---------------- tf32 GEMM tile body ----------------
// block = 256 threads = 8 warps; block tile = 64 rows x 128 cols.
// warp = 16 rows x 64 cols: rows 16*(warp&3), cols 64*(warp>>2).
// EPI=true : relu+rownorm epilogue -> fp32 out (cross-warp row stats via smem).
// EPI=false: raw accumulators -> fp16 y1h.
template <bool EPI>
__device__ __forceinline__ void gemm_body(
    int blk, const float* __restrict__ X, const float* __restrict__ W,
    const float* __restrict__ b, const float* __restrict__ off,
    const float* __restrict__ sc, float* __restrict__ out,
    __half* __restrict__ outh, unsigned* smem_u)
{
    unsigned* sW = smem_u;                 // 128 x PW tf32
    unsigned* sX = smem_u + 128 * PW;      // 64 x PW tf32
    float* sStats = (float*)(smem_u + 192 * PW);  // [64 rows][2 halves][sum,sq]

    const int warp = threadIdx.x >> 5, lane = threadIdx.x & 31;
    const int gid = lane >> 2, tig = lane & 3;
    const int rowBase = blk * 64;

    // load W (128x32 float4), convert to tf32, padded store
    for (int i = threadIdx.x; i < 128 * 32; i += 256) {
        int r = i >> 5, c4 = (i & 31) * 4;
        float4 v = ((const float4*)W)[i];
        unsigned* p = sW + r * PW + c4;
        p[0] = f2tf32(v.x); p[1] = f2tf32(v.y);
        p[2] = f2tf32(v.z); p[3] = f2tf32(v.w);
    }
    // load X tile (64x32 float4), zero-pad tail rows
    for (int i = threadIdx.x; i < 64 * 32; i += 256) {
        int r = i >> 5, c4 = (i & 31) * 4;
        float4 v = make_float4(0.f, 0.f, 0.f, 0.f);
        int gr = rowBase + r;
        if (gr < NN) v = ((const float4*)(X + (size_t)gr * 128))[c4 >> 2];
        unsigned* p = sX + r * PW + c4;
        p[0] = f2tf32(v.x); p[1] = f2tf32(v.y);
        p[2] = f2tf32(v.z); p[3] = f2tf32(v.w);
    }
    __syncthreads();

    float4 acc[8];
    #pragma unroll
    for (int t = 0; t < 8; t++) acc[t] = make_float4(0.f, 0.f, 0.f, 0.f);

    const int rLoc = (warp & 3) * 16;      // row stripe within 64
    const int cBase = (warp >> 2) * 64;    // col half

    #pragma unroll 1
    for (int ks = 0; ks < 16; ks++) {
        int k0 = ks * 8;
        unsigned a0 = sX[(rLoc + gid)     * PW + k0 + tig];
        unsigned a1 = sX[(rLoc + gid + 8) * PW + k0 + tig];
        unsigned a2 = sX[(rLoc + gid)     * PW + k0 + tig + 4];
        unsigned a3 = sX[(rLoc + gid + 8) * PW + k0 + tig + 4];
        #pragma unroll
        for (int t = 0; t < 8; t++) {
            int nc = cBase + 8 * t + gid;
            unsigned b0 = sW[(k0 + tig)     * PW + nc];
            unsigned b1 = sW[(k0 + tig + 4) * PW + nc];
            mma_tf32(acc[t], a0, a1, a2, a3, b0, b1);
        }
    }

    // fragment rows: r0 = rLoc+gid, r1 = r0+8 ; cols per t: cBase+8t+2*tig, +1
    const int rloc0 = rLoc + gid, rloc1 = rloc0 + 8;
    const int grow0 = rowBase + rloc0, grow1 = rowBase + rloc1;

    if (EPI) {
        float2 bv[8], scv[8], ofv[8];
        #pragma unroll
        for (int t = 0; t < 8; t++) {
            int col = cBase + 8 * t + 2 * tig;
            bv[t]  = *(const float2*)(b  + col);
            scv[t] = *(const float2*)(sc + col);
            ofv[t] = *(const float2*)(off + col);
        }
        float ps0 = 0.f, pq0 = 0.f, ps1 = 0.f, pq1 = 0.f;
        #pragma unroll
        for (int t = 0; t < 8; t++) {
            acc[t].x = fmaxf(acc[t].x + bv[t].x, 0.f);
            acc[t].y = fmaxf(acc[t].y + bv[t].y, 0.f);
            acc[t].z = fmaxf(acc[t].z + bv[t].x, 0.f);
            acc[t].w = fmaxf(acc[t].w + bv[t].y, 0.f);
            ps0 += acc[t].x + acc[t].y;
            pq0 += acc[t].x * acc[t].x + acc[t].y * acc[t].y;
            ps1 += acc[t].z + acc[t].w;
            pq1 += acc[t].z * acc[t].z + acc[t].w * acc[t].w;
        }
        // reduce over the 4 lanes of each row group (tig axis)
        #pragma unroll
        for (int o = 1; o < 4; o <<= 1) {
            ps0 += __shfl_xor_sync(0xffffffffu, ps0, o);
            pq0 += __shfl_xor_sync(0xffffffffu, pq0, o);
            ps1 += __shfl_xor_sync(0xffffffffu, ps1, o);
            pq1 += __shfl_xor_sync(0xffffffffu, pq1, o);
        }
        const int half = warp >> 2;
        if (tig == 0) {
            sStats[rloc0 * 4 + half * 2 + 0] = ps0;
            sStats[rloc0 * 4 + half * 2 + 1] = pq0;
            sStats[rloc1 * 4 + half * 2 + 0] = ps1;
            sStats[rloc1 * 4 + half * 2 + 1] = pq1;
        }
        __syncthreads();
        float sum0 = sStats[rloc0 * 4 + 0] + sStats[rloc0 * 4 + 2];
        float sq0  = sStats[rloc0 * 4 + 1] + sStats[rloc0 * 4 + 3];
        float sum1 = sStats[rloc1 * 4 + 0] + sStats[rloc1 * 4 + 2];
        float sq1  = sStats[rloc1 * 4 + 1] + sStats[rloc1 * 4 + 3];
        float mean0 = sum0 * (1.f / 128.f);
        float mean1 = sum1 * (1.f / 128.f);
        float inv0 = rsqrtf(fmaxf(sq0 * (1.f / 128.f) - mean0 * mean0, 0.f) + 1e-9f);
        float inv1 = rsqrtf(fmaxf(sq1 * (1.f / 128.f) - mean1 * mean1, 0.f) + 1e-9f);
        #pragma unroll
        for (int t = 0; t < 8; t++) {
            int col = cBase + 8 * t + 2 * tig;
            if (grow0 < NN) {
                float2 o2;
                o2.x = (acc[t].x - mean0) * scv[t].x * inv0 + ofv[t].x;
                o2.y = (acc[t].y - mean0) * scv[t].y * inv0 + ofv[t].y;
                *(float2*)(out + (size_t)grow0 * 128 + col) = o2;
            }
            if (grow1 < NN) {
                float2 o2;
                o2.x = (acc[t].z - mean1) * scv[t].x * inv1 + ofv[t].x;
                o2.y = (acc[t].w - mean1) * scv[t].y * inv1 + ofv[t].y;
                *(float2*)(out + (size_t)grow1 * 128 + col) = o2;
            }
        }
    } else {
        #pragma unroll
        for (int t = 0; t < 8; t++) {
            int col = cBase + 8 * t + 2 * tig;
            if (grow0 < NN) {
                __half2 h = __floats2half2_rn(acc[t].x, acc[t].y);
                *(__half2*)(outh + (size_t)grow0 * 128 + col) = h;
            }
            if (grow1 < NN) {
                __half2 h = __floats2half2_rn(acc[t].z, acc[t].w);
                *(__half2*)(outh + (size_t)grow1 * 128 + col) = h;
            }
        }
    }
}

// ---------------- fused middle kernel: {gemm_p0, gemm_y1, scatter} concurrently ----
// 1:1 interleave: even blocks do one 64-row tf32 GEMM tile, odd blocks scatter
// 1024 edges. grid = 2 * 2 * TB = 6252. 2*TB*1024 = 3,201,024 >= EE.
__global__ __launch_bounds__(256) void fused_mid(
    const float* __restrict__ feat,
    const float* __restrict__ W0, const float* __restrict__ b0,
    const float* __restrict__ off0, const float* __restrict__ sc0,
    const float* __restrict__ W1,
    const int* __restrict__ rows, const int* __restrict__ cols,
    const float* __restrict__ vals,
    float* __restrict__ out, __half* __restrict__ y1h)
{
    extern __shared__ unsigned smem_u[];
    int bid = blockIdx.x;
    int g = bid >> 1;
    if ((bid & 1) == 0) {
        if (g < TB) gemm_body<true >(g,      feat, W0, b0, off0, sc0, out, nullptr, smem_u);
        else        gemm_body<false>(g - TB, feat, W1, nullptr, nullptr, nullptr, nullptr, y1h, smem_u);
    } else {
        int base = g * 1024 + (int)threadIdx.x;
        #pragma unroll
        for (int j = 0; j < 4; j++) {
            int e = base + j * 256;
            if (e < EE) {
                int rr = rows[e];
                int p = atomicAdd(&g_cursor[rr], 1);
                g_epack[p] = make_uint2((unsigned)cols[e], __float_as_uint(vals[e]));
            }
        }
    }
}

// ---------------- SpMM gather + fused epilogue: out[r] += norm(relu(A@y1 + b1)) ----
__global__ __launch_bounds__(256) void spmm_kernel(
    const float* __restrict__ b, const float* __restrict__ off,
    const float* __restrict__ sc, float* __restrict__ out)
{
    int gw = (blockIdx.x * blockDim.x + threadIdx.x) >> 5;
    if (gw >= NN) return;
    int lane = threadIdx.x & 31;
    int start = g_off[gw];
    int deg   = g_deg[gw];

    float4 acc = make_float4(0.f, 0.f, 0.f, 0.f);
    for (int base = 0; base < deg; base += 32) {
        int idx = base + lane;
        uint2 ew = make_uint2(0u, 0u);
        if (idx < deg) ew = g_epack[start + idx];
        int m = min(32, deg - base);
        #pragma unroll 4
        for (int j = 0; j < m; j++) {
            int   cj = (int)__shfl_sync(0xffffffffu, ew.x, j);
            float wj = __int_as_float(__shfl_sync(0xffffffffu, ew.y, j));
            uint2 yv = ((const uint2*)(g_y1h + (size_t)cj * 128))[lane];
            __half2 h01 = *(__half2*)&yv.x;
            __half2 h23 = *(__half2*)&yv.y;
            float2 f01 = __half22float2(h01);
            float2 f23 = __half22float2(h23);
            acc.x = fmaf(wj, f01.x, acc.x);
            acc.y = fmaf(wj, f01.y, acc.y);
            acc.z = fmaf(wj, f23.x, acc.z);
            acc.w = fmaf(wj, f23.y, acc.w);
        }
    }

    float4 bv  = *(const float4*)(b  + 4 * lane);
    float4 scv = *(const float4*)(sc + 4 * lane);
    float4 ofv = *(const float4*)(off + 4 * lane);
    float h0 = fmaxf(acc.x + bv.x, 0.f);
    float h1 = fmaxf(acc.y + bv.y, 0.f);
    float h2 = fmaxf(acc.z + bv.z, 0.f);
    float h3 = fmaxf(acc.w + bv.w, 0.f);
    float s = h0 + h1 + h2 + h3;
    #pragma unroll
    for (int o = 16; o; o >>= 1) s += __shfl_xor_sync(0xffffffffu, s, o);
    float mean = s * (1.f / 128.f);
    float d0 = h0 - mean, d1 = h1 - mean, d2 = h2 - mean, d3 = h3 - mean;
    float q = d0 * d0 + d1 * d1 + d2 * d2 + d3 * d3;
    #pragma unroll
    for (int o = 16; o; o >>= 1) q += __shfl_xor_sync(0xffffffffu, q, o);
    float inv = rsqrtf(q * (1.f / 128.f) + 1e-9f);

    float* orow = out + (size_t)gw * 128 + 4 * lane;
    float4 prev = *(float4*)orow;
    float4 o4;
    o4.x = prev.x + d0 * scv.x * inv + ofv.x;
    o4.y = prev.y + d1 * scv.y * inv + ofv.y;
    o4.z = prev.z + d2 * scv.z * inv + ofv.z;
    o4.w = prev.w + d3 * scv.w * inv + ofv.w;
    *(float4*)orow = o4;
}

// ---------------- launcher ----------------
extern "C" void kernel_launch(void* const* d_in, const int* in_sizes, int n_in,
                              void* d_out, int out_size)
{
    const float* feat = (const float*)d_in[0];
    const float* vals = (const float*)d_in[1];
    const float* W0   = (const float*)d_in[2];
    const float* b0   = (const float*)d_in[3];
    const float* off0 = (const float*)d_in[4];
    const float* sc0  = (const float*)d_in[5];
    const float* W1   = (const float*)d_in[6];
    const float* b1   = (const float*)d_in[7];
    const float* off1 = (const float*)d_in[8];
    const float* sc1  = (const float*)d_in[9];
    const int*   rows = (const int*)d_in[10];
    const int*   cols = (const int*)d_in[11];
    float* out = (float*)d_out;

    // smem: (128+64)*PW tf32 words + 64*2*2 stat floats
    const int smem = (192 * PW + 256) * (int)sizeof(unsigned);  // 102400 B
    cudaFuncSetAttribute(fused_mid, cudaFuncAttributeMaxDynamicSharedMemorySize, smem);

    // ---- CSR front chain (serial, small) ----
    k_zero_deg<<<(NN + 255) / 256, 256>>>();
    k_hist<<<(EE + 255) / 256, 256>>>(rows);
    int nblk = (NN + 1023) / 1024;           // 98
    {
        int* offp;  cudaGetSymbolAddress((void**)&offp,  g_off);
        int* degp;  cudaGetSymbolAddress((void**)&degp,  g_deg);
        int* bsump; cudaGetSymbolAddress((void**)&bsump, g_bsum);
        k_scan_block<<<nblk, 1024>>>(degp, offp, bsump, NN);
        k_scan_block<<<1, 1024>>>(bsump, bsump, nullptr, nblk);
    }
    k_finalize_off<<<(NN + 255) / 256, 256>>>();

    // ---- fused middle: both tf32 GEMMs + edge scatter concurrently ----
    __half* y1p; cudaGetSymbolAddress((void**)&y1p, g_y1h);
    fused_mid<<<2 * 2 * TB, 256, smem>>>(feat, W0, b0, off0, sc0, W1,
                                         rows, cols, vals, out, y1p);

    // ---- sparse aggregate + fused p1 epilogue, out += p1 ----
    int sblocks = ((NN * 32) + 255) / 256;   // one warp per row
    spmm_kernel<<<sblocks, 256>>>(b1, off1, sc1, out);
}